// round 1
// baseline (speedup 1.0000x reference)
#include <cuda_runtime.h>
#include <math.h>

#define NWIN 4096

__device__ float g_dsx[NWIN * 96];
__device__ float g_wts[NWIN * 3];
__device__ int   g_nbr[NWIN * 3];

// ---------------------------------------------------------------------------
// Kernel A: per-window max pool  x[B,C,256,256] -> dsx[4096][96]
// block = (gy, c, b), 256 threads = one image row segment of 8 windows x 8 rows
// ---------------------------------------------------------------------------
__global__ void __launch_bounds__(256) ka_pool(const float* __restrict__ x) {
    const int gy = blockIdx.x, c = blockIdx.y, b = blockIdx.z;
    const float* row = x + ((((b * 96 + c) * 256) + gy * 8) << 8);
    const int t = threadIdx.x;
    float m = row[t];
#pragma unroll
    for (int r = 1; r < 8; ++r) m = fmaxf(m, row[(r << 8) + t]);
    m = fmaxf(m, __shfl_xor_sync(0xffffffffu, m, 1));
    m = fmaxf(m, __shfl_xor_sync(0xffffffffu, m, 2));
    m = fmaxf(m, __shfl_xor_sync(0xffffffffu, m, 4));
    if ((t & 7) == 0) {
        const int gx = t >> 3;
        g_dsx[(b * 1024 + gy * 32 + gx) * 96 + c] = m;
    }
}

// ---------------------------------------------------------------------------
// Kernel B: global similarity + top-3 + softmax weights
// 256 blocks x 16 queries; tiles of 256 keys; 4x4 register outer products.
// ---------------------------------------------------------------------------
__device__ __forceinline__ void ins3(float d, int j, float v[3], int id[3]) {
    if (d > v[0]) { v[2]=v[1]; id[2]=id[1]; v[1]=v[0]; id[1]=id[0]; v[0]=d; id[0]=j; }
    else if (d > v[1]) { v[2]=v[1]; id[2]=id[1]; v[1]=d; id[1]=j; }
    else if (d > v[2]) { v[2]=d; id[2]=j; }
}

#define KB_SMEM ((96 * 260 + 96 * 20) * 4)

__global__ void __launch_bounds__(256) kb_top3() {
    extern __shared__ float sm[];
    float* jT = sm;             // [96][260]  keys transposed, padded
    float* qT = sm + 96 * 260;  // [96][20]   queries transposed, padded

    const int t = threadIdx.x;
    const int q0 = blockIdx.x << 4;

    for (int i = t; i < 16 * 96; i += 256) {
        int ql = i / 96, c = i - ql * 96;
        qT[c * 20 + ql] = g_dsx[(q0 + ql) * 96 + c];
    }
    __syncthreads();

    const int qg = t >> 6;      // 0..3  (4 queries each)
    const int jg = t & 63;      // 0..63 (4 keys each per tile)

    float v[4][3]; int id[4][3];
#pragma unroll
    for (int a = 0; a < 4; ++a)
#pragma unroll
        for (int r = 0; r < 3; ++r) { v[a][r] = -3.4e38f; id[a][r] = 0; }

    for (int T = 0; T < 16; ++T) {
        for (int i = t; i < 256 * 96; i += 256) {
            int jl = i / 96, c = i - jl * 96;
            jT[c * 260 + jl] = g_dsx[((T << 8) + jl) * 96 + c];
        }
        __syncthreads();

        float acc[4][4];
#pragma unroll
        for (int a = 0; a < 4; ++a)
#pragma unroll
            for (int r = 0; r < 4; ++r) acc[a][r] = 0.f;

#pragma unroll 2
        for (int c = 0; c < 96; ++c) {
            float4 a4 = *(const float4*)(qT + c * 20 + (qg << 2));
            float4 b4 = *(const float4*)(jT + c * 260 + (jg << 2));
            float av[4] = {a4.x, a4.y, a4.z, a4.w};
            float bv[4] = {b4.x, b4.y, b4.z, b4.w};
#pragma unroll
            for (int a = 0; a < 4; ++a)
#pragma unroll
                for (int r = 0; r < 4; ++r) acc[a][r] = fmaf(av[a], bv[r], acc[a][r]);
        }
        const int jb = (T << 8) + (jg << 2);
#pragma unroll
        for (int a = 0; a < 4; ++a) {
            ins3(acc[a][0], jb + 0, v[a], id[a]);
            ins3(acc[a][1], jb + 1, v[a], id[a]);
            ins3(acc[a][2], jb + 2, v[a], id[a]);
            ins3(acc[a][3], jb + 3, v[a], id[a]);
        }
        __syncthreads();
    }

    // merge: per query 64 partial top-3 lists (alias jT storage)
    float* mv = sm;
    int*   mi = (int*)(sm + 16 * 192);
#pragma unroll
    for (int a = 0; a < 4; ++a) {
        int q = (qg << 2) + a;
#pragma unroll
        for (int r = 0; r < 3; ++r) {
            mv[(q * 64 + jg) * 3 + r] = v[a][r];
            mi[(q * 64 + jg) * 3 + r] = id[a][r];
        }
    }
    __syncthreads();

    if (t < 16) {
        float bv3[3] = {-3.4e38f, -3.4e38f, -3.4e38f};
        int   bi3[3] = {0x7fffffff, 0x7fffffff, 0x7fffffff};
        for (int e = 0; e < 192; ++e) {
            float d = mv[t * 192 + e]; int j = mi[t * 192 + e];
            if (d > bv3[0] || (d == bv3[0] && j < bi3[0])) {
                bv3[2]=bv3[1]; bi3[2]=bi3[1]; bv3[1]=bv3[0]; bi3[1]=bi3[0]; bv3[0]=d; bi3[0]=j;
            } else if (d > bv3[1] || (d == bv3[1] && j < bi3[1])) {
                bv3[2]=bv3[1]; bi3[2]=bi3[1]; bv3[1]=d; bi3[1]=j;
            } else if (d > bv3[2] || (d == bv3[2] && j < bi3[2])) {
                bv3[2]=d; bi3[2]=j;
            }
        }
        const float m = bv3[0];
        const float e0 = 1.f, e1 = expf(bv3[1] - m), e2 = expf(bv3[2] - m);
        const float s = 1.f / (e0 + e1 + e2);
        const int q = q0 + t;
        g_wts[q * 3 + 0] = e0 * s; g_wts[q * 3 + 1] = e1 * s; g_wts[q * 3 + 2] = e2 * s;
        g_nbr[q * 3 + 0] = bi3[0]; g_nbr[q * 3 + 1] = bi3[1]; g_nbr[q * 3 + 2] = bi3[2];
    }
}

// ---------------------------------------------------------------------------
// Kernel C: fused per-window context gather + QKV + attention + lepe + proj
// 4096 blocks x 256 threads, ~217 KB smem
// ---------------------------------------------------------------------------
__device__ __forceinline__ int win_base(int m) {
    const int bb = m >> 10, yy = (m >> 5) & 31, xx = m & 31;
    return ((bb * 96) << 16) + (yy << 11) + (xx << 3);
}

template <int KDIM>
__device__ __forceinline__ void gemm_core(const float* __restrict__ A,    // [KDIM][68]
                                          const float* __restrict__ Bm,   // [KDIM][100]
                                          const float* __restrict__ bias, // [96] or null
                                          int tp, int tco, float acc[4][6]) {
#pragma unroll
    for (int j = 0; j < 6; ++j) {
        const float bb = bias ? bias[tco + j] : 0.f;
        acc[0][j] = bb; acc[1][j] = bb; acc[2][j] = bb; acc[3][j] = bb;
    }
#pragma unroll 4
    for (int k = 0; k < KDIM; ++k) {
        const float4 a4 = *(const float4*)(A + k * 68 + tp);
        const float av[4] = {a4.x, a4.y, a4.z, a4.w};
#pragma unroll
        for (int j = 0; j < 6; ++j) {
            const float w = Bm[k * 100 + tco + j];
#pragma unroll
            for (int i = 0; i < 4; ++i) acc[i][j] = fmaf(av[i], w, acc[i][j]);
        }
    }
}

#define KC_SMEM (54336 * 4)

__global__ void __launch_bounds__(256) kc_main(
    const float* __restrict__ x,
    const float* __restrict__ Wq, const float* __restrict__ bq,
    const float* __restrict__ Wk, const float* __restrict__ bk,
    const float* __restrict__ Wv, const float* __restrict__ bv,
    const float* __restrict__ Wp, const float* __restrict__ bp,
    const float* __restrict__ lepe_w, const float* __restrict__ lepe_b,
    float* __restrict__ out)
{
    extern __shared__ float sm[];
    float* xs = sm;                 // [96][68]   window tokens [c][p]
    float* cx = xs + 96 * 68;       // [96][68]   context [c][p]
    float* ws = cx + 96 * 68;       // [96][100]  staged weight [k][co]
    float* qT = ws + 96 * 100;      // [96][68]   q transposed [c][p]
    float* kT = qT + 96 * 68;       // [96][68]   k transposed [c][j]
    float* vs = kT + 96 * 68;       // [64][100]  v [j][c]
    float* ss = vs + 64 * 100;      // [64][68]   attn transposed [j][p]
    float* os = ss + 64 * 68;       // [96][68]   attn-out + lepe [c][p]
    float* lw = os + 96 * 68;       // 96*9
    float* lb = lw + 864;           // 96
    float* cb = lb + 96;            // 4*96: bq,bk,bv,bp

    const int t = threadIdx.x;
    const int n = blockIdx.x;
    const int b = n >> 10, gy = (n >> 5) & 31, gx = n & 31;

    const float w0 = g_wts[n * 3 + 0], w1 = g_wts[n * 3 + 1], w2 = g_wts[n * 3 + 2];
    const int i0 = g_nbr[n * 3 + 0], i1 = g_nbr[n * 3 + 1], i2 = g_nbr[n * 3 + 2];
    const int bx = win_base(n), nb0 = win_base(i0), nb1 = win_base(i1), nb2 = win_base(i2);

    for (int i = t; i < 864; i += 256) lw[i] = lepe_w[i];
    if (t < 96) {
        lb[t] = lepe_b[t];
        cb[t] = bq[t]; cb[96 + t] = bk[t]; cb[192 + t] = bv[t]; cb[288 + t] = bp[t];
    }

    for (int i = t; i < 96 * 64; i += 256) {
        const int c = i >> 6, p = i & 63;
        const int off = (c << 16) + ((p >> 3) << 8) + (p & 7);
        xs[c * 68 + p] = x[bx + off];
        cx[c * 68 + p] = w0 * x[nb0 + off] + w1 * x[nb1 + off] + w2 * x[nb2 + off];
    }
    __syncthreads();

    const int pg = t >> 4, cg = t & 15;
    const int tp = pg << 2, tco = cg * 6;

#define LOADW(Wg) do { for (int i = t; i < 9216; i += 256) { int k = i / 96, co = i - k * 96; ws[k * 100 + co] = (Wg)[i]; } } while (0)

    // ---- Q = xs^T Wq + bq -> qT[c][p]
    LOADW(Wq); __syncthreads();
    {
        float acc[4][6];
        gemm_core<96>(xs, ws, cb, tp, tco, acc);
#pragma unroll
        for (int j = 0; j < 6; ++j)
#pragma unroll
            for (int i = 0; i < 4; ++i) qT[(tco + j) * 68 + tp + i] = acc[i][j];
    }
    __syncthreads();

    // ---- K = cx^T Wk + bk -> kT[c][j]
    LOADW(Wk); __syncthreads();
    {
        float acc[4][6];
        gemm_core<96>(cx, ws, cb + 96, tp, tco, acc);
#pragma unroll
        for (int j = 0; j < 6; ++j)
#pragma unroll
            for (int i = 0; i < 4; ++i) kT[(tco + j) * 68 + tp + i] = acc[i][j];
    }
    __syncthreads();

    // ---- V = cx^T Wv + bv -> vs[j][c]
    LOADW(Wv); __syncthreads();
    {
        float acc[4][6];
        gemm_core<96>(cx, ws, cb + 192, tp, tco, acc);
#pragma unroll
        for (int j = 0; j < 6; ++j)
#pragma unroll
            for (int i = 0; i < 4; ++i) vs[(tp + i) * 100 + tco + j] = acc[i][j];
    }
    __syncthreads();

    // ---- scores: ss[j][p] = scale * sum_c q[c][p] k[c][j]
    {
        const int tj = (t & 15) << 2;
        float acc[4][4];
#pragma unroll
        for (int i = 0; i < 4; ++i)
#pragma unroll
            for (int j = 0; j < 4; ++j) acc[i][j] = 0.f;
#pragma unroll 2
        for (int c = 0; c < 96; ++c) {
            const float4 a4 = *(const float4*)(qT + c * 68 + tp);
            const float4 k4 = *(const float4*)(kT + c * 68 + tj);
            const float av[4] = {a4.x, a4.y, a4.z, a4.w};
            const float kv[4] = {k4.x, k4.y, k4.z, k4.w};
#pragma unroll
            for (int i = 0; i < 4; ++i)
#pragma unroll
                for (int j = 0; j < 4; ++j) acc[i][j] = fmaf(av[i], kv[j], acc[i][j]);
        }
        const float scl = 0.10206207261596576f;  // 96^-0.5
#pragma unroll
        for (int i = 0; i < 4; ++i)
#pragma unroll
            for (int j = 0; j < 4; ++j) ss[(tj + j) * 68 + tp + i] = acc[i][j] * scl;
    }
    __syncthreads();

    // ---- softmax over j (columns of ss) — 4 threads per token p
    {
        const int pc = t >> 2, s0 = (t & 3) << 4;
        float mx = -3.4e38f;
#pragma unroll
        for (int jj = 0; jj < 16; ++jj) mx = fmaxf(mx, ss[(s0 + jj) * 68 + pc]);
        mx = fmaxf(mx, __shfl_xor_sync(0xffffffffu, mx, 1));
        mx = fmaxf(mx, __shfl_xor_sync(0xffffffffu, mx, 2));
        float sum = 0.f;
#pragma unroll
        for (int jj = 0; jj < 16; ++jj) {
            const float e = __expf(ss[(s0 + jj) * 68 + pc] - mx);
            ss[(s0 + jj) * 68 + pc] = e;
            sum += e;
        }
        sum += __shfl_xor_sync(0xffffffffu, sum, 1);
        sum += __shfl_xor_sync(0xffffffffu, sum, 2);
        const float inv = 1.f / sum;
#pragma unroll
        for (int jj = 0; jj < 16; ++jj) ss[(s0 + jj) * 68 + pc] *= inv;
    }
    __syncthreads();

    // ---- out = attn @ v (+ lepe) -> os[c][p]
    {
        float acc[4][6];
        gemm_core<64>(ss, vs, (const float*)0, tp, tco, acc);
#pragma unroll
        for (int j = 0; j < 6; ++j) {
            const int c = tco + j;
            const float* wc = lw + c * 9;
            const float* xc = xs + c * 68;
#pragma unroll
            for (int i = 0; i < 4; ++i) {
                const int p = tp + i, py = p >> 3, px = p & 7;
                float s = lb[c];
#pragma unroll
                for (int dy = 0; dy < 3; ++dy) {
                    const int yy = py + dy - 1;
                    if (yy < 0 || yy > 7) continue;
#pragma unroll
                    for (int dx = 0; dx < 3; ++dx) {
                        const int xx = px + dx - 1;
                        if (xx < 0 || xx > 7) continue;
                        s = fmaf(xc[(yy << 3) + xx], wc[dy * 3 + dx], s);
                    }
                }
                os[c * 68 + p] = acc[i][j] + s;
            }
        }
    }
    __syncthreads();

    // ---- final projection + store
    LOADW(Wp); __syncthreads();
    {
        float acc[4][6];
        gemm_core<96>(os, ws, cb + 288, tp, tco, acc);
        const int py = tp >> 3, px = tp & 7;
        float* obase = out + ((b * 96) << 16) + (((gy << 3) + py) << 8) + (gx << 3) + px;
#pragma unroll
        for (int j = 0; j < 6; ++j) {
            float4 r = make_float4(acc[0][j], acc[1][j], acc[2][j], acc[3][j]);
            *(float4*)(obase + ((tco + j) << 16)) = r;
        }
    }
#undef LOADW
}

// ---------------------------------------------------------------------------
extern "C" void kernel_launch(void* const* d_in, const int* in_sizes, int n_in,
                              void* d_out, int out_size) {
    (void)in_sizes; (void)n_in; (void)out_size;
    const float* x  = (const float*)d_in[0];
    const float* Wq = (const float*)d_in[1];
    const float* bq = (const float*)d_in[2];
    const float* Wk = (const float*)d_in[3];
    const float* bk = (const float*)d_in[4];
    const float* Wv = (const float*)d_in[5];
    const float* bv = (const float*)d_in[6];
    const float* Wp = (const float*)d_in[7];
    const float* bp = (const float*)d_in[8];
    const float* lw = (const float*)d_in[9];
    const float* lb = (const float*)d_in[10];
    float* out = (float*)d_out;

    cudaFuncSetAttribute(kb_top3, cudaFuncAttributeMaxDynamicSharedMemorySize, KB_SMEM);
    cudaFuncSetAttribute(kc_main, cudaFuncAttributeMaxDynamicSharedMemorySize, KC_SMEM);

    ka_pool<<<dim3(32, 96, 4), 256>>>(x);
    kb_top3<<<256, 256, KB_SMEM>>>();
    kc_main<<<4096, 256, KC_SMEM>>>(x, Wq, bq, Wk, bk, Wv, bv, Wp, bp, lw, lb, out);
}

// round 4
// speedup vs baseline: 1.0004x; 1.0004x over previous
#include <cuda_runtime.h>
#include <math.h>

#define NWIN 4096

__device__ float g_dsx[NWIN * 96];
__device__ float g_wts[NWIN * 3];
__device__ int   g_nbr[NWIN * 3];

// ---------------------------------------------------------------------------
// Kernel A: per-window max pool  x[B,C,256,256] -> dsx[4096][96]
// block = (gy, c, b), 256 threads = one image row segment of 8 windows x 8 rows
// ---------------------------------------------------------------------------
__global__ void __launch_bounds__(256) ka_pool(const float* __restrict__ x) {
    const int gy = blockIdx.x, c = blockIdx.y, b = blockIdx.z;
    const float* row = x + ((((b * 96 + c) * 256) + gy * 8) << 8);
    const int t = threadIdx.x;
    float m = row[t];
#pragma unroll
    for (int r = 1; r < 8; ++r) m = fmaxf(m, row[(r << 8) + t]);
    m = fmaxf(m, __shfl_xor_sync(0xffffffffu, m, 1));
    m = fmaxf(m, __shfl_xor_sync(0xffffffffu, m, 2));
    m = fmaxf(m, __shfl_xor_sync(0xffffffffu, m, 4));
    if ((t & 7) == 0) {
        const int gx = t >> 3;
        g_dsx[(b * 1024 + gy * 32 + gx) * 96 + c] = m;
    }
}

// ---------------------------------------------------------------------------
// Kernel B: global similarity + top-3 + softmax weights
// 256 blocks x 16 queries; tiles of 256 keys; 4x4 register outer products.
// ---------------------------------------------------------------------------
__device__ __forceinline__ void ins3(float d, int j, float v[3], int id[3]) {
    if (d > v[0]) { v[2]=v[1]; id[2]=id[1]; v[1]=v[0]; id[1]=id[0]; v[0]=d; id[0]=j; }
    else if (d > v[1]) { v[2]=v[1]; id[2]=id[1]; v[1]=d; id[1]=j; }
    else if (d > v[2]) { v[2]=d; id[2]=j; }
}

#define KB_SMEM ((96 * 260 + 96 * 20) * 4)

__global__ void __launch_bounds__(256) kb_top3() {
    extern __shared__ float sm[];
    float* jT = sm;             // [96][260]  keys transposed, padded
    float* qT = sm + 96 * 260;  // [96][20]   queries transposed, padded

    const int t = threadIdx.x;
    const int q0 = blockIdx.x << 4;

    for (int i = t; i < 16 * 96; i += 256) {
        int ql = i / 96, c = i - ql * 96;
        qT[c * 20 + ql] = g_dsx[(q0 + ql) * 96 + c];
    }
    __syncthreads();

    const int qg = t >> 6;      // 0..3  (4 queries each)
    const int jg = t & 63;      // 0..63 (4 keys each per tile)

    float v[4][3]; int id[4][3];
#pragma unroll
    for (int a = 0; a < 4; ++a)
#pragma unroll
        for (int r = 0; r < 3; ++r) { v[a][r] = -3.4e38f; id[a][r] = 0; }

    for (int T = 0; T < 16; ++T) {
        for (int i = t; i < 256 * 96; i += 256) {
            int jl = i / 96, c = i - jl * 96;
            jT[c * 260 + jl] = g_dsx[((T << 8) + jl) * 96 + c];
        }
        __syncthreads();

        float acc[4][4];
#pragma unroll
        for (int a = 0; a < 4; ++a)
#pragma unroll
            for (int r = 0; r < 4; ++r) acc[a][r] = 0.f;

#pragma unroll 2
        for (int c = 0; c < 96; ++c) {
            float4 a4 = *(const float4*)(qT + c * 20 + (qg << 2));
            float4 b4 = *(const float4*)(jT + c * 260 + (jg << 2));
            float av[4] = {a4.x, a4.y, a4.z, a4.w};
            float bv[4] = {b4.x, b4.y, b4.z, b4.w};
#pragma unroll
            for (int a = 0; a < 4; ++a)
#pragma unroll
                for (int r = 0; r < 4; ++r) acc[a][r] = fmaf(av[a], bv[r], acc[a][r]);
        }
        const int jb = (T << 8) + (jg << 2);
#pragma unroll
        for (int a = 0; a < 4; ++a) {
            ins3(acc[a][0], jb + 0, v[a], id[a]);
            ins3(acc[a][1], jb + 1, v[a], id[a]);
            ins3(acc[a][2], jb + 2, v[a], id[a]);
            ins3(acc[a][3], jb + 3, v[a], id[a]);
        }
        __syncthreads();
    }

    // merge: per query 64 partial top-3 lists (alias jT storage)
    float* mv = sm;
    int*   mi = (int*)(sm + 16 * 192);
#pragma unroll
    for (int a = 0; a < 4; ++a) {
        int q = (qg << 2) + a;
#pragma unroll
        for (int r = 0; r < 3; ++r) {
            mv[(q * 64 + jg) * 3 + r] = v[a][r];
            mi[(q * 64 + jg) * 3 + r] = id[a][r];
        }
    }
    __syncthreads();

    if (t < 16) {
        float bv3[3] = {-3.4e38f, -3.4e38f, -3.4e38f};
        int   bi3[3] = {0x7fffffff, 0x7fffffff, 0x7fffffff};
        for (int e = 0; e < 192; ++e) {
            float d = mv[t * 192 + e]; int j = mi[t * 192 + e];
            if (d > bv3[0] || (d == bv3[0] && j < bi3[0])) {
                bv3[2]=bv3[1]; bi3[2]=bi3[1]; bv3[1]=bv3[0]; bi3[1]=bi3[0]; bv3[0]=d; bi3[0]=j;
            } else if (d > bv3[1] || (d == bv3[1] && j < bi3[1])) {
                bv3[2]=bv3[1]; bi3[2]=bi3[1]; bv3[1]=d; bi3[1]=j;
            } else if (d > bv3[2] || (d == bv3[2] && j < bi3[2])) {
                bv3[2]=d; bi3[2]=j;
            }
        }
        const float m = bv3[0];
        const float e0 = 1.f, e1 = expf(bv3[1] - m), e2 = expf(bv3[2] - m);
        const float s = 1.f / (e0 + e1 + e2);
        const int q = q0 + t;
        g_wts[q * 3 + 0] = e0 * s; g_wts[q * 3 + 1] = e1 * s; g_wts[q * 3 + 2] = e2 * s;
        g_nbr[q * 3 + 0] = bi3[0]; g_nbr[q * 3 + 1] = bi3[1]; g_nbr[q * 3 + 2] = bi3[2];
    }
}

// ---------------------------------------------------------------------------
// Kernel C: fused per-window context gather + QKV + attention + lepe + proj
// 4096 blocks x 256 threads, ~217 KB smem
// ---------------------------------------------------------------------------
__device__ __forceinline__ int win_base(int m) {
    const int bb = m >> 10, yy = (m >> 5) & 31, xx = m & 31;
    return ((bb * 96) << 16) + (yy << 11) + (xx << 3);
}

template <int KDIM>
__device__ __forceinline__ void gemm_core(const float* __restrict__ A,    // [KDIM][68]
                                          const float* __restrict__ Bm,   // [KDIM][100]
                                          const float* __restrict__ bias, // [96] or null
                                          int tp, int tco, float acc[4][6]) {
#pragma unroll
    for (int j = 0; j < 6; ++j) {
        const float bb = bias ? bias[tco + j] : 0.f;
        acc[0][j] = bb; acc[1][j] = bb; acc[2][j] = bb; acc[3][j] = bb;
    }
#pragma unroll 4
    for (int k = 0; k < KDIM; ++k) {
        const float4 a4 = *(const float4*)(A + k * 68 + tp);
        const float av[4] = {a4.x, a4.y, a4.z, a4.w};
#pragma unroll
        for (int j = 0; j < 6; ++j) {
            const float w = Bm[k * 100 + tco + j];
#pragma unroll
            for (int i = 0; i < 4; ++i) acc[i][j] = fmaf(av[i], w, acc[i][j]);
        }
    }
}

#define KC_SMEM (54336 * 4)

__global__ void __launch_bounds__(256) kc_main(
    const float* __restrict__ x,
    const float* __restrict__ Wq, const float* __restrict__ bq,
    const float* __restrict__ Wk, const float* __restrict__ bk,
    const float* __restrict__ Wv, const float* __restrict__ bv,
    const float* __restrict__ Wp, const float* __restrict__ bp,
    const float* __restrict__ lepe_w, const float* __restrict__ lepe_b,
    float* __restrict__ out)
{
    extern __shared__ float sm[];
    float* xs = sm;                 // [96][68]   window tokens [c][p]
    float* cx = xs + 96 * 68;       // [96][68]   context [c][p]
    float* ws = cx + 96 * 68;       // [96][100]  staged weight [k][co]
    float* qT = ws + 96 * 100;      // [96][68]   q transposed [c][p]
    float* kT = qT + 96 * 68;       // [96][68]   k transposed [c][j]
    float* vs = kT + 96 * 68;       // [64][100]  v [j][c]
    float* ss = vs + 64 * 100;      // [64][68]   attn transposed [j][p]
    float* os = ss + 64 * 68;       // [96][68]   attn-out + lepe [c][p]
    float* lw = os + 96 * 68;       // 96*9
    float* lb = lw + 864;           // 96
    float* cb = lb + 96;            // 4*96: bq,bk,bv,bp

    const int t = threadIdx.x;
    const int n = blockIdx.x;
    const int b = n >> 10, gy = (n >> 5) & 31, gx = n & 31;

    const float w0 = g_wts[n * 3 + 0], w1 = g_wts[n * 3 + 1], w2 = g_wts[n * 3 + 2];
    const int i0 = g_nbr[n * 3 + 0], i1 = g_nbr[n * 3 + 1], i2 = g_nbr[n * 3 + 2];
    const int bx = win_base(n), nb0 = win_base(i0), nb1 = win_base(i1), nb2 = win_base(i2);

    for (int i = t; i < 864; i += 256) lw[i] = lepe_w[i];
    if (t < 96) {
        lb[t] = lepe_b[t];
        cb[t] = bq[t]; cb[96 + t] = bk[t]; cb[192 + t] = bv[t]; cb[288 + t] = bp[t];
    }

    for (int i = t; i < 96 * 64; i += 256) {
        const int c = i >> 6, p = i & 63;
        const int off = (c << 16) + ((p >> 3) << 8) + (p & 7);
        xs[c * 68 + p] = x[bx + off];
        cx[c * 68 + p] = w0 * x[nb0 + off] + w1 * x[nb1 + off] + w2 * x[nb2 + off];
    }
    __syncthreads();

    const int pg = t >> 4, cg = t & 15;
    const int tp = pg << 2, tco = cg * 6;

#define LOADW(Wg) do { for (int i = t; i < 9216; i += 256) { int k = i / 96, co = i - k * 96; ws[k * 100 + co] = (Wg)[i]; } } while (0)

    // ---- Q = xs^T Wq + bq -> qT[c][p]
    LOADW(Wq); __syncthreads();
    {
        float acc[4][6];
        gemm_core<96>(xs, ws, cb, tp, tco, acc);
#pragma unroll
        for (int j = 0; j < 6; ++j)
#pragma unroll
            for (int i = 0; i < 4; ++i) qT[(tco + j) * 68 + tp + i] = acc[i][j];
    }
    __syncthreads();

    // ---- K = cx^T Wk + bk -> kT[c][j]
    LOADW(Wk); __syncthreads();
    {
        float acc[4][6];
        gemm_core<96>(cx, ws, cb + 96, tp, tco, acc);
#pragma unroll
        for (int j = 0; j < 6; ++j)
#pragma unroll
            for (int i = 0; i < 4; ++i) kT[(tco + j) * 68 + tp + i] = acc[i][j];
    }
    __syncthreads();

    // ---- V = cx^T Wv + bv -> vs[j][c]
    LOADW(Wv); __syncthreads();
    {
        float acc[4][6];
        gemm_core<96>(cx, ws, cb + 192, tp, tco, acc);
#pragma unroll
        for (int j = 0; j < 6; ++j)
#pragma unroll
            for (int i = 0; i < 4; ++i) vs[(tp + i) * 100 + tco + j] = acc[i][j];
    }
    __syncthreads();

    // ---- scores: ss[j][p] = scale * sum_c q[c][p] k[c][j]
    {
        const int tj = (t & 15) << 2;
        float acc[4][4];
#pragma unroll
        for (int i = 0; i < 4; ++i)
#pragma unroll
            for (int j = 0; j < 4; ++j) acc[i][j] = 0.f;
#pragma unroll 2
        for (int c = 0; c < 96; ++c) {
            const float4 a4 = *(const float4*)(qT + c * 68 + tp);
            const float4 k4 = *(const float4*)(kT + c * 68 + tj);
            const float av[4] = {a4.x, a4.y, a4.z, a4.w};
            const float kv[4] = {k4.x, k4.y, k4.z, k4.w};
#pragma unroll
            for (int i = 0; i < 4; ++i)
#pragma unroll
                for (int j = 0; j < 4; ++j) acc[i][j] = fmaf(av[i], kv[j], acc[i][j]);
        }
        const float scl = 0.10206207261596576f;  // 96^-0.5
#pragma unroll
        for (int i = 0; i < 4; ++i)
#pragma unroll
            for (int j = 0; j < 4; ++j) ss[(tj + j) * 68 + tp + i] = acc[i][j] * scl;
    }
    __syncthreads();

    // ---- softmax over j (columns of ss) — 4 threads per token p
    {
        const int pc = t >> 2, s0 = (t & 3) << 4;
        float mx = -3.4e38f;
#pragma unroll
        for (int jj = 0; jj < 16; ++jj) mx = fmaxf(mx, ss[(s0 + jj) * 68 + pc]);
        mx = fmaxf(mx, __shfl_xor_sync(0xffffffffu, mx, 1));
        mx = fmaxf(mx, __shfl_xor_sync(0xffffffffu, mx, 2));
        float sum = 0.f;
#pragma unroll
        for (int jj = 0; jj < 16; ++jj) {
            const float e = __expf(ss[(s0 + jj) * 68 + pc] - mx);
            ss[(s0 + jj) * 68 + pc] = e;
            sum += e;
        }
        sum += __shfl_xor_sync(0xffffffffu, sum, 1);
        sum += __shfl_xor_sync(0xffffffffu, sum, 2);
        const float inv = 1.f / sum;
#pragma unroll
        for (int jj = 0; jj < 16; ++jj) ss[(s0 + jj) * 68 + pc] *= inv;
    }
    __syncthreads();

    // ---- out = attn @ v (+ lepe) -> os[c][p]
    {
        float acc[4][6];
        gemm_core<64>(ss, vs, (const float*)0, tp, tco, acc);
#pragma unroll
        for (int j = 0; j < 6; ++j) {
            const int c = tco + j;
            const float* wc = lw + c * 9;
            const float* xc = xs + c * 68;
#pragma unroll
            for (int i = 0; i < 4; ++i) {
                const int p = tp + i, py = p >> 3, px = p & 7;
                float s = lb[c];
#pragma unroll
                for (int dy = 0; dy < 3; ++dy) {
                    const int yy = py + dy - 1;
                    if (yy < 0 || yy > 7) continue;
#pragma unroll
                    for (int dx = 0; dx < 3; ++dx) {
                        const int xx = px + dx - 1;
                        if (xx < 0 || xx > 7) continue;
                        s = fmaf(xc[(yy << 3) + xx], wc[dy * 3 + dx], s);
                    }
                }
                os[c * 68 + p] = acc[i][j] + s;
            }
        }
    }
    __syncthreads();

    // ---- final projection + store
    LOADW(Wp); __syncthreads();
    {
        float acc[4][6];
        gemm_core<96>(os, ws, cb + 288, tp, tco, acc);
        const int py = tp >> 3, px = tp & 7;
        float* obase = out + ((b * 96) << 16) + (((gy << 3) + py) << 8) + (gx << 3) + px;
#pragma unroll
        for (int j = 0; j < 6; ++j) {
            float4 r = make_float4(acc[0][j], acc[1][j], acc[2][j], acc[3][j]);
            *(float4*)(obase + ((tco + j) << 16)) = r;
        }
    }
#undef LOADW
}

// ---------------------------------------------------------------------------
extern "C" void kernel_launch(void* const* d_in, const int* in_sizes, int n_in,
                              void* d_out, int out_size) {
    (void)in_sizes; (void)n_in; (void)out_size;
    const float* x  = (const float*)d_in[0];
    const float* Wq = (const float*)d_in[1];
    const float* bq = (const float*)d_in[2];
    const float* Wk = (const float*)d_in[3];
    const float* bk = (const float*)d_in[4];
    const float* Wv = (const float*)d_in[5];
    const float* bv = (const float*)d_in[6];
    const float* Wp = (const float*)d_in[7];
    const float* bp = (const float*)d_in[8];
    const float* lw = (const float*)d_in[9];
    const float* lb = (const float*)d_in[10];
    float* out = (float*)d_out;

    cudaFuncSetAttribute(kb_top3, cudaFuncAttributeMaxDynamicSharedMemorySize, KB_SMEM);
    cudaFuncSetAttribute(kc_main, cudaFuncAttributeMaxDynamicSharedMemorySize, KC_SMEM);

    ka_pool<<<dim3(32, 96, 4), 256>>>(x);
    kb_top3<<<256, 256, KB_SMEM>>>();
    kc_main<<<4096, 256, KC_SMEM>>>(x, Wq, bq, Wk, bk, Wv, bv, Wp, bp, lw, lb, out);
}